// round 9
// baseline (speedup 1.0000x reference)
#include <cuda_runtime.h>
#include <math_constants.h>

// StratifiedMaxPooling: out[b,c] = max_{j: labels[j]==c} values[b,j]
// values: [B=128, N=200000] f32, labels: [N] int32, C=100.
//
// R9: transpose-staged conflict-free scatter, TILE=128.
//  - 2 blocks/SM (512 thr), each owns 64 rows; double-buffered 128-col stage,
//    ONE barrier per tile (4x fewer barriers/value than R8's TILE=32-era).
//  - Class grouping: warp g owns columns with (class & 15) == g; equal-label
//    columns land in one warp by construction. Lane covers rows {lane,
//    lane+32}; same-class repeats are same-lane => thread-ordered, race-free.
//  - Four 32-col ballots merged into TWO 64-bit masks, stripped 1+1 col per
//    iteration (two independent ffs->LDS->RMW chains for ILP). Drained mask
//    redirects writes to pad class 100 (never flushed, benign).
//  - Bank-conflict-free: stage pitch 65, acc pitch 101 (both coprime to 32).
//  - Single kernel: unsigned keys, zero-init g_keys valid; last block decodes
//    to out and self-resets for graph replay.

#define FULL 0xFFFFFFFFu

static const int NTHR    = 512;    // 16 warps
static const int ROWS_PB = 64;
static const int C_NUM   = 100;
static const int C_PAD   = 101;
static const int NOUT    = 128 * C_NUM;     // 12800
static const int TILE    = 128;
static const int RPITCH  = 65;
static const int NSTREAM = 148;
static const int STG_F   = TILE * RPITCH;   // floats per stage buffer

__device__ unsigned g_keys[NOUT];  // zero static init; self-cleaning
__device__ unsigned g_done;        // zero static init; self-cleaning

__device__ __forceinline__ unsigned ukey(float f) {
    int x = __float_as_int(f);
    return (unsigned)(x ^ ((x >> 31) | 0x80000000));
}
__device__ __forceinline__ float udecode(unsigned u) {
    unsigned m = ((int)u < 0) ? 0x80000000u : 0xFFFFFFFFu;
    return __int_as_float((int)(u ^ m));
}

__global__ __launch_bounds__(NTHR, 2)
void pool_kernel(const float* __restrict__ values,
                 const int*   __restrict__ labels,
                 float* __restrict__ out, int N, int ntiles)
{
    extern __shared__ float sdyn[];
    float* const stage = sdyn;                       // [2][TILE*RPITCH]
    int*   const scl   = (int*)(sdyn + 2 * STG_F);   // [2][TILE]
    __shared__ float acc[ROWS_PB * C_PAD];           // 25.9 KB
    __shared__ int   s_last;

    const int tid  = threadIdx.x;
    const int lane = tid & 31;
    const int warp = tid >> 5;                 // column group id (0..15)
    const int half = blockIdx.x & 1;
    const int strm = blockIdx.x >> 1;

    for (int i = tid; i < ROWS_PB * C_PAD; i += NTHR) acc[i] = -CUDART_INF_F;

    // load mapping: thread -> row (tid>>3), quads at cols 4q+32s, s=0..3
    const int lrow = tid >> 3;
    const int q4   = (tid & 7) * 4;
    const float* const vrow = values + (size_t)(half * ROWS_PB + lrow) * N;
    int sof[4];
#pragma unroll
    for (int s = 0; s < 4; s++) sof[s] = (q4 + 32 * s) * RPITCH + lrow;

    float* const accA = acc + lane * C_PAD;
    float* const accB = acc + (lane + 32) * C_PAD;

    // ---- prologue: stage tile t0 into buf0; prefetch t0+NSTREAM into regs
    int t = strm;
    {
        const float* vt = vrow + (size_t)t * TILE;
#pragma unroll
        for (int s = 0; s < 4; s++) {
            float4 v = __ldcs(reinterpret_cast<const float4*>(vt + q4 + 32 * s));
            float* sp = stage + sof[s];
            sp[0] = v.x; sp[RPITCH] = v.y;
            sp[2 * RPITCH] = v.z; sp[3 * RPITCH] = v.w;
        }
        if (tid < TILE) scl[tid] = labels[t * TILE + tid];
    }
    int    t1 = t + NSTREAM;
    bool   h1 = t1 < ntiles;
    float4 pv[4];
#pragma unroll
    for (int s = 0; s < 4; s++) pv[s] = make_float4(0.f, 0.f, 0.f, 0.f);
    int pl = 0;
    if (h1) {
        const float* vt = vrow + (size_t)t1 * TILE;
#pragma unroll
        for (int s = 0; s < 4; s++)
            pv[s] = __ldcs(reinterpret_cast<const float4*>(vt + q4 + 32 * s));
        if (tid < TILE) pl = labels[t1 * TILE + tid];
    }
    __syncthreads();   // buf0 + acc ready

    int p = 0;
    for (; t < ntiles; t += NSTREAM) {
        // store prefetched tile into buf 1-p
        if (h1) {
            float* sb = stage + (1 - p) * STG_F;
#pragma unroll
            for (int s = 0; s < 4; s++) {
                float* sp = sb + sof[s];
                sp[0] = pv[s].x; sp[RPITCH] = pv[s].y;
                sp[2 * RPITCH] = pv[s].z; sp[3 * RPITCH] = pv[s].w;
            }
            if (tid < TILE) scl[(1 - p) * TILE + tid] = pl;
        }
        // prefetch t+2*NSTREAM (overlaps processing below)
        const int t2 = t + 2 * NSTREAM;
        const bool h2 = t2 < ntiles;
        if (h2) {
            const float* vt = vrow + (size_t)t2 * TILE;
#pragma unroll
            for (int s = 0; s < 4; s++)
                pv[s] = __ldcs(reinterpret_cast<const float4*>(vt + q4 + 32 * s));
            if (tid < TILE) pl = labels[t2 * TILE + tid];
        }
        h1 = h2;

        // ---- process tile t from buf p
        {
            const float* const stg = stage + p * STG_F;
            const int*   const scp = scl + p * TILE;
            const int cls0 = scp[lane];
            const int cls1 = scp[lane + 32];
            const int cls2 = scp[lane + 64];
            const int cls3 = scp[lane + 96];
            const unsigned b0 = __ballot_sync(FULL, (cls0 & 15) == warp);
            const unsigned b1 = __ballot_sync(FULL, (cls1 & 15) == warp);
            const unsigned b2 = __ballot_sync(FULL, (cls2 & 15) == warp);
            const unsigned b3 = __ballot_sync(FULL, (cls3 & 15) == warp);
            unsigned long long mA =
                (unsigned long long)b0 | ((unsigned long long)b1 << 32);
            unsigned long long mB =
                (unsigned long long)b2 | ((unsigned long long)b3 << 32);

            while (mA | mB) {
                int cA = __ffsll((long long)mA) - 1;  // col in [0,64)
                int cB = __ffsll((long long)mB) - 1;  // col-64 in [0,64)
                cA = mA ? cA : 0;
                cB = mB ? cB : 0;
                int kA = scp[cA];          // broadcast LDS
                int kB = scp[64 + cB];
                kA = mA ? kA : 100;        // drained -> pad class (benign)
                kB = mB ? kB : 100;
                mA &= mA - 1;              // safe when 0: stays 0
                mB &= mB - 1;
                const float* sA = stg + cA * RPITCH;
                const float* sB = stg + (64 + cB) * RPITCH;
                const float xA0 = sA[lane], xA1 = sA[lane + 32];
                const float xB0 = sB[lane], xB1 = sB[lane + 32];
                float* a0 = accA + kA; float* a1 = accB + kA;
                float* d0 = accA + kB; float* d1 = accB + kB;
                *a0 = fmaxf(*a0, xA0);
                *a1 = fmaxf(*a1, xA1);
                *d0 = fmaxf(*d0, xB0);   // kB==kA repeats are same-lane:
                *d1 = fmaxf(*d1, xB1);   // thread-ordered, race-free
            }
        }
        __syncthreads();   // buf 1-p stores done; buf p reads done
        p ^= 1;
    }

    // ---- remainder columns (N % TILE): stream-0 blocks via global atomics
    const int remstart = ntiles * TILE;
    if (remstart < N && strm == 0) {
        const int rem = N - remstart;
        for (int i = tid; i < rem * ROWS_PB; i += NTHR) {
            const int r = i / rem;
            const int j = remstart + (i - r * rem);
            const int grow = half * ROWS_PB + r;
            atomicMax(&g_keys[grow * C_NUM + labels[j]],
                      ukey(values[(size_t)grow * N + j]));
        }
    }

    // ---- flush block partials
    for (int i = tid; i < ROWS_PB * C_NUM; i += NTHR) {
        const int r = i / C_NUM;
        const int c = i - r * C_NUM;
        atomicMax(&g_keys[(half * ROWS_PB + r) * C_NUM + c],
                  ukey(acc[r * C_PAD + c]));
    }
    __threadfence();
    __syncthreads();
    if (tid == 0)
        s_last = (atomicAdd(&g_done, 1u) == (unsigned)(gridDim.x - 1));
    __syncthreads();

    // ---- last block: decode to output, self-reset for graph replays
    if (s_last) {
        for (int i = tid; i < NOUT; i += NTHR) {
            out[i] = udecode(__ldcg(&g_keys[i]));
            g_keys[i] = 0u;
        }
        __threadfence();
        if (tid == 0) g_done = 0u;
    }
}

extern "C" void kernel_launch(void* const* d_in, const int* in_sizes, int n_in,
                              void* d_out, int out_size)
{
    const float* values = (const float*)d_in[0];
    const int*   labels = (const int*)d_in[1];
    const int N = in_sizes[1];        // 200000
    const int ntiles = N / TILE;      // 1562

    const int dyn_bytes = (2 * STG_F) * (int)sizeof(float)
                        + (2 * TILE) * (int)sizeof(int);   // 67584 B
    cudaFuncSetAttribute(pool_kernel,
                         cudaFuncAttributeMaxDynamicSharedMemorySize,
                         dyn_bytes);

    pool_kernel<<<2 * NSTREAM, NTHR, dyn_bytes>>>(values, labels,
                                                  (float*)d_out, N, ntiles);
}

// round 12
// speedup vs baseline: 1.0226x; 1.0226x over previous
#include <cuda_runtime.h>
#include <math_constants.h>

// StratifiedMaxPooling: out[b,c] = max_{j: labels[j]==c} values[b,j]
// values: [B=128, N=200000] f32, labels: [N] int32, C=100.
//
// R12 = R11 with the REAL launch-failure fix: R10/R11 dropped the
// cudaFuncSetAttribute opt-in, but static(acc 27.5KB) + dynamic(35.3KB)
// smem = 62.8KB > 48KB default per-block limit -> launch "out of
// resources" (unchecked) -> latched error killed graph capture.
// Now ALL shared memory is dynamic (62.8KB) with the opt-in attribute set.
//
// Design (from R10):
//  - 2 blocks/SM (512 thr); block owns 64 rows, TILE=64 cols, double-buffered
//    stage, ONE barrier per tile.
//  - acc CLASS-MAJOR [class][row], pitch 68. Lane l covers rows {2l, 2l+1}:
//    one float2 LDS + 2 FMNMX + one float2 STS per column covers 64 rows,
//    bank-conflict-free.
//  - Warp g owns columns with (class & 15) == g => same-class columns always
//    same warp & lane => thread-ordered, race-free. Dual 32-bit mask chains
//    for ILP; drained chain redirects to pad class 100; kA==kB chained.
//  - Single kernel: unsigned keys, zero-init g_keys; last block decodes and
//    self-resets for graph replay.

#define FULL 0xFFFFFFFFu

static const int NTHR    = 512;    // 16 warps
static const int ROWS_PB = 64;     // rows per block
static const int C_NUM   = 100;
static const int NOUT    = 128 * C_NUM;   // 12800
static const int TILE    = 64;     // columns per tile
static const int RP      = 68;     // pitch (stage rows & acc rows), even
static const int STG_F   = TILE * RP;     // 4352 floats per stage buffer
static const int ACC_F   = (C_NUM + 1) * RP;   // 6868 floats
static const int NSTREAM = 148;

__device__ unsigned g_keys[NOUT];  // zero static init; self-cleaning
__device__ unsigned g_done;        // zero static init; self-cleaning

__device__ __forceinline__ unsigned ukey(float f) {
    int x = __float_as_int(f);
    return (unsigned)(x ^ ((x >> 31) | 0x80000000));
}
__device__ __forceinline__ float udecode(unsigned u) {
    unsigned m = ((int)u < 0) ? 0x80000000u : 0xFFFFFFFFu;
    return __int_as_float((int)(u ^ m));
}

__global__ __launch_bounds__(NTHR, 2)
void pool_kernel(const float* __restrict__ values,
                 const int*   __restrict__ labels,
                 float* __restrict__ out, int N, int ntiles)
{
    extern __shared__ __align__(16) float sdyn[];
    float* const stage = sdyn;                        // [2][STG_F] col-major
    float* const acc   = sdyn + 2 * STG_F;            // [class][row] + pad cls
    int*   const scl   = (int*)(sdyn + 2 * STG_F + ACC_F);  // [2][TILE]
    __shared__ int s_last;

    const int tid  = threadIdx.x;
    const int lane = tid & 31;
    const int warp = tid >> 5;                 // class group id (0..15)
    const int half = blockIdx.x & 1;
    const int strm = blockIdx.x >> 1;

    for (int i = tid; i < ACC_F; i += NTHR) acc[i] = -CUDART_INF_F;

    // ---- fill mapping: warp w -> rows 8*(w&7)..+7, colq block (w>>3)
    const int rl   = lane >> 2;
    const int q    = lane & 3;
    const int rowl = 8 * (warp & 7) + rl;            // 0..63
    const float* const vrow = values + (size_t)(half * ROWS_PB + rowl) * N;
    const int col0  = 4 * (4 * (warp >> 3) + q);     // local col of float4
    const int soff0 = col0 * RP + rowl;              // stage offset (floats)

    // ---- prologue: stage tile t0 into buf0; prefetch t0+NSTREAM into regs
    int t = strm;
    if (t < ntiles) {
        const float* vt = vrow + (size_t)t * TILE;
#pragma unroll
        for (int j = 0; j < 2; j++) {
            float4 v = __ldcs(reinterpret_cast<const float4*>(vt + col0 + 32 * j));
            float* sp = stage + soff0 + 32 * j * RP;
            sp[0] = v.x; sp[RP] = v.y; sp[2 * RP] = v.z; sp[3 * RP] = v.w;
        }
        if (tid < TILE) scl[tid] = labels[t * TILE + tid];
    }
    int    t1 = t + NSTREAM;
    bool   h1 = t1 < ntiles;
    float4 pv0 = make_float4(0.f, 0.f, 0.f, 0.f), pv1 = pv0;
    int    pl  = 0;
    if (h1) {
        const float* vt = vrow + (size_t)t1 * TILE;
        pv0 = __ldcs(reinterpret_cast<const float4*>(vt + col0));
        pv1 = __ldcs(reinterpret_cast<const float4*>(vt + col0 + 32));
        if (tid < TILE) pl = labels[t1 * TILE + tid];
    }
    __syncthreads();   // acc init + buf0 ready

    int p = 0;
    for (; t < ntiles; t += NSTREAM) {
        // store prefetched tile into buf 1-p
        if (h1) {
            float* sb = stage + (1 - p) * STG_F + soff0;
            sb[0] = pv0.x; sb[RP] = pv0.y; sb[2*RP] = pv0.z; sb[3*RP] = pv0.w;
            sb += 32 * RP;
            sb[0] = pv1.x; sb[RP] = pv1.y; sb[2*RP] = pv1.z; sb[3*RP] = pv1.w;
            if (tid < TILE) scl[(1 - p) * TILE + tid] = pl;
        }
        // prefetch t+2*NSTREAM (overlaps processing below)
        const int t2 = t + 2 * NSTREAM;
        const bool h2 = t2 < ntiles;
        if (h2) {
            const float* vt = vrow + (size_t)t2 * TILE;
            pv0 = __ldcs(reinterpret_cast<const float4*>(vt + col0));
            pv1 = __ldcs(reinterpret_cast<const float4*>(vt + col0 + 32));
            if (tid < TILE) pl = labels[t2 * TILE + tid];
        }
        h1 = h2;

        // ---- process tile t from buf p
        {
            const float* const stg = stage + p * STG_F;
            const int*   const scp = scl + p * TILE;
            const int clsA = scp[lane];         // col = lane
            const int clsB = scp[32 + lane];    // col = 32 + lane
            unsigned mA = __ballot_sync(FULL, (clsA & 15) == warp);
            unsigned mB = __ballot_sync(FULL, (clsB & 15) == warp);

            while (mA | mB) {
                int cA = mA ? (__ffs((int)mA) - 1) : 0;
                int cB = mB ? (__ffs((int)mB) - 1) : 0;
                int kA = mA ? scp[cA]      : C_NUM;   // pad class redirect
                int kB = mB ? scp[32 + cB] : C_NUM;
                mA &= mA - 1;
                mB &= mB - 1;
                const float2 xA = *reinterpret_cast<const float2*>(
                    stg + cA * RP + 2 * lane);
                const float2 xB = *reinterpret_cast<const float2*>(
                    stg + (32 + cB) * RP + 2 * lane);
                float2* const aA = reinterpret_cast<float2*>(
                    acc + kA * RP + 2 * lane);
                float2* const aB = reinterpret_cast<float2*>(
                    acc + kB * RP + 2 * lane);
                float2 vA = *aA;
                float2 vB = *aB;
                vA.x = fmaxf(vA.x, xA.x);
                vA.y = fmaxf(vA.y, xA.y);
                // same-class collision across the two chains: chain B off A
                if (kA == kB) vB = vA;
                vB.x = fmaxf(vB.x, xB.x);
                vB.y = fmaxf(vB.y, xB.y);
                *aA = vA;     // if kA==kB, aB write lands last with both
                *aB = vB;
            }
        }
        __syncthreads();   // buf 1-p stores done; buf p reads done
        p ^= 1;
    }

    // ---- remainder columns (N % TILE == 0 here; kept for generality)
    const int remstart = ntiles * TILE;
    if (remstart < N && strm == 0) {
        const int rem = N - remstart;
        for (int i = tid; i < rem * ROWS_PB; i += NTHR) {
            const int r = i / rem;
            const int j = remstart + (i - r * rem);
            const int grow = half * ROWS_PB + r;
            atomicMax(&g_keys[grow * C_NUM + labels[j]],
                      ukey(values[(size_t)grow * N + j]));
        }
    }

    __syncthreads();       // all acc writes visible to flush readers

    // ---- flush block partials (rotated start staggers same-addr atomics)
    {
        const int rot = (blockIdx.x * 1051) % (ROWS_PB * C_NUM);
        for (int i = tid; i < ROWS_PB * C_NUM; i += NTHR) {
            int i2 = i + rot;
            if (i2 >= ROWS_PB * C_NUM) i2 -= ROWS_PB * C_NUM;
            const int r = i2 / C_NUM;
            const int c = i2 - r * C_NUM;
            atomicMax(&g_keys[(half * ROWS_PB + r) * C_NUM + c],
                      ukey(acc[c * RP + r]));
        }
    }
    __threadfence();
    __syncthreads();
    if (tid == 0)
        s_last = (atomicAdd(&g_done, 1u) == (unsigned)(gridDim.x - 1));
    __syncthreads();

    // ---- last block: decode to output, self-reset for graph replays
    if (s_last) {
        for (int i = tid; i < NOUT; i += NTHR) {
            out[i] = udecode(__ldcg(&g_keys[i]));
            g_keys[i] = 0u;
        }
        __threadfence();
        if (tid == 0) g_done = 0u;
    }
}

extern "C" void kernel_launch(void* const* d_in, const int* in_sizes, int n_in,
                              void* d_out, int out_size)
{
    const float* values = (const float*)d_in[0];
    const int*   labels = (const int*)d_in[1];
    const int N = in_sizes[1];        // 200000
    const int ntiles = N / TILE;      // 3125

    const int dyn_bytes = (2 * STG_F + ACC_F) * (int)sizeof(float)
                        + 2 * TILE * (int)sizeof(int);   // 62800 B
    cudaFuncSetAttribute(pool_kernel,
                         cudaFuncAttributeMaxDynamicSharedMemorySize,
                         dyn_bytes);

    pool_kernel<<<2 * NSTREAM, NTHR, dyn_bytes>>>(values, labels,
                                                  (float*)d_out, N, ntiles);
}

// round 13
// speedup vs baseline: 1.1426x; 1.1174x over previous
#include <cuda_runtime.h>
#include <math_constants.h>

// StratifiedMaxPooling: out[b,c] = max_{j: labels[j]==c} values[b,j]
// values: [B=128, N=200000] f32, labels: [N] int32, C=100.
//
// R13 = R8 (best: 41.5us) + occupancy: 3 CTAs/SM instead of 2.
//  - R8 profile was latency-bound (occ 46%, nothing saturated); smem
//    59.7KB/block allows 3 CTAs/SM (179KB), regs 40 <= 42.6 OK.
//  - grid = 2 halves x 222 streams = 444 = 3 per SM; three independent
//    barrier domains per SM decorrelate per-tile barrier waits.
//  - Inner loop is R8's scalar 2-column-batched form (beat both the 64-bit
//    mask variant R9 and the float2 variant R12).
//  - Flush start rotated per block to stagger same-address atomicMax.

#define FULL 0xFFFFFFFFu

static const int NTHR    = 512;    // 16 warps
static const int ROWS_PB = 64;     // rows per block
static const int C_NUM   = 100;
static const int C_PAD   = 101;    // acc pitch
static const int NOUT    = 128 * C_NUM;   // 12800
static const int TILE    = 64;     // columns per tile
static const int RPITCH  = 65;     // stage row pitch
static const int NSTREAM = 222;    // tile stride (grid = 2*NSTREAM = 444)

__device__ unsigned g_keys[NOUT];  // zero static init; self-cleaning
__device__ unsigned g_done;        // zero static init; self-cleaning

__device__ __forceinline__ unsigned ukey(float f) {
    int x = __float_as_int(f);
    return (unsigned)(x ^ ((x >> 31) | 0x80000000));
}
__device__ __forceinline__ float udecode(unsigned u) {
    unsigned m = ((int)u < 0) ? 0x80000000u : 0xFFFFFFFFu;
    return __int_as_float((int)(u ^ m));
}

__global__ __launch_bounds__(NTHR, 3)
void pool_kernel(const float* __restrict__ values,
                 const int*   __restrict__ labels,
                 float* __restrict__ out, int N, int ntiles)
{
    __shared__ float stage[2][TILE * RPITCH];  // 2 x 16.6 KB
    __shared__ int   scl[2][TILE];
    __shared__ float acc[ROWS_PB * C_PAD];     // 25.9 KB
    __shared__ int   s_last;

    const int tid  = threadIdx.x;
    const int lane = tid & 31;
    const int warp = tid >> 5;                 // == column group id (0..15)
    const int half = blockIdx.x & 1;
    const int strm = blockIdx.x >> 1;

    for (int i = tid; i < ROWS_PB * C_PAD; i += NTHR) acc[i] = -CUDART_INF_F;

    // ---- load mapping: thread -> row (tid>>3), two 4-col quads (q, q+8)
    const int lrow = tid >> 3;
    const int q    = tid & 7;
    const float* const vrow = values + (size_t)(half * ROWS_PB + lrow) * N;
    const int cqa = 4 * q;             // cols cqa..cqa+3
    const int cqb = 4 * (q + 8);       // cols cqb..cqb+3
    const int sofa = cqa * RPITCH + lrow;
    const int sofb = cqb * RPITCH + lrow;

    // ---- process mapping
    float* const accA = acc + lane * C_PAD;
    float* const accB = acc + (lane + 32) * C_PAD;

    // ---- prologue: stage tile t0 into buf0; prefetch t0+NSTREAM into regs
    int t = strm;
    if (t < ntiles) {
        const float* vt = vrow + (size_t)t * TILE;
        float4 a = __ldcs(reinterpret_cast<const float4*>(vt + cqa));
        float4 b = __ldcs(reinterpret_cast<const float4*>(vt + cqb));
        float* sa = &stage[0][sofa];
        float* sb = &stage[0][sofb];
        sa[0] = a.x; sa[RPITCH] = a.y; sa[2*RPITCH] = a.z; sa[3*RPITCH] = a.w;
        sb[0] = b.x; sb[RPITCH] = b.y; sb[2*RPITCH] = b.z; sb[3*RPITCH] = b.w;
        if (tid < TILE) scl[0][tid] = labels[t * TILE + tid];
    }
    int    t1 = t + NSTREAM;
    bool   h1 = t1 < ntiles;
    float4 va = make_float4(0.f,0.f,0.f,0.f), vb = va;
    int    l1 = 0;
    if (h1) {
        const float* vt = vrow + (size_t)t1 * TILE;
        va = __ldcs(reinterpret_cast<const float4*>(vt + cqa));
        vb = __ldcs(reinterpret_cast<const float4*>(vt + cqb));
        if (tid < TILE) l1 = labels[t1 * TILE + tid];
    }
    __syncthreads();   // buf0 + acc ready

    int p = 0;
    for (; t < ntiles; t += NSTREAM) {
        // store prefetched tile into buf 1-p
        if (h1) {
            float* sa = &stage[1 - p][sofa];
            float* sb = &stage[1 - p][sofb];
            sa[0]=va.x; sa[RPITCH]=va.y; sa[2*RPITCH]=va.z; sa[3*RPITCH]=va.w;
            sb[0]=vb.x; sb[RPITCH]=vb.y; sb[2*RPITCH]=vb.z; sb[3*RPITCH]=vb.w;
            if (tid < TILE) scl[1 - p][tid] = l1;
        }
        // prefetch t+2*NSTREAM (overlaps processing below)
        const int t2 = t + 2 * NSTREAM;
        const bool h2 = t2 < ntiles;
        if (h2) {
            const float* vt = vrow + (size_t)t2 * TILE;
            va = __ldcs(reinterpret_cast<const float4*>(vt + cqa));
            vb = __ldcs(reinterpret_cast<const float4*>(vt + cqb));
            if (tid < TILE) l1 = labels[t2 * TILE + tid];
        }
        h1 = h2;

        // ---- process tile t from buf p: two 32-column sub-tiles
        const float* const stg = stage[p];
#pragma unroll
        for (int sub = 0; sub < 2; sub++) {
            const int cls = scl[p][sub * 32 + lane];
            unsigned mask = __ballot_sync(FULL, (cls & 15) == warp);
            const float* const sbase = stg + (sub * 32) * RPITCH;
            while (mask) {
                const int c0 = __ffs((int)mask) - 1; mask &= mask - 1;
                int c1 = c0;
                if (mask) { c1 = __ffs((int)mask) - 1; mask &= mask - 1; }
                const int k0 = __shfl_sync(FULL, cls, c0);
                const int k1 = __shfl_sync(FULL, cls, c1);
                const float* s0 = sbase + c0 * RPITCH;
                const float* s1 = sbase + c1 * RPITCH;
                const float x0a = s0[lane], x0b = s0[lane + 32];
                const float x1a = s1[lane], x1b = s1[lane + 32];
                float* p0a = accA + k0;  float* p0b = accB + k0;
                float* p1a = accA + k1;  float* p1b = accB + k1;
                // c1==c0 repeat is same-lane => thread-ordered, still correct
                *p0a = fmaxf(*p0a, x0a);
                *p0b = fmaxf(*p0b, x0b);
                *p1a = fmaxf(*p1a, x1a);
                *p1b = fmaxf(*p1b, x1b);
            }
        }
        __syncthreads();   // buf 1-p stores done; buf p reads done
        p ^= 1;
    }

    // ---- remainder columns (N % 64 == 0 here; kept for generality)
    const int remstart = ntiles * TILE;
    if (remstart < N && strm == 0) {
        const int rem = N - remstart;
        for (int i = tid; i < rem * ROWS_PB; i += NTHR) {
            const int r = i / rem;
            const int j = remstart + (i - r * rem);
            const int grow = half * ROWS_PB + r;
            atomicMax(&g_keys[grow * C_NUM + labels[j]],
                      ukey(values[(size_t)grow * N + j]));
        }
    }

    // ---- flush block partials (rotated start staggers same-addr atomics)
    {
        const int rot = (blockIdx.x * 1051) % (ROWS_PB * C_NUM);
        for (int i = tid; i < ROWS_PB * C_NUM; i += NTHR) {
            int i2 = i + rot;
            if (i2 >= ROWS_PB * C_NUM) i2 -= ROWS_PB * C_NUM;
            const int r = i2 / C_NUM;
            const int c = i2 - r * C_NUM;
            atomicMax(&g_keys[(half * ROWS_PB + r) * C_NUM + c],
                      ukey(acc[r * C_PAD + c]));
        }
    }
    __threadfence();
    __syncthreads();
    if (tid == 0)
        s_last = (atomicAdd(&g_done, 1u) == (unsigned)(gridDim.x - 1));
    __syncthreads();

    // ---- last block: decode to output, self-reset for graph replays
    if (s_last) {
        for (int i = tid; i < NOUT; i += NTHR) {
            out[i] = udecode(__ldcg(&g_keys[i]));
            g_keys[i] = 0u;
        }
        __threadfence();
        if (tid == 0) g_done = 0u;
    }
}

extern "C" void kernel_launch(void* const* d_in, const int* in_sizes, int n_in,
                              void* d_out, int out_size)
{
    const float* values = (const float*)d_in[0];
    const int*   labels = (const int*)d_in[1];
    const int N = in_sizes[1];        // 200000
    const int ntiles = N / TILE;      // 3125

    pool_kernel<<<2 * NSTREAM, NTHR>>>(values, labels, (float*)d_out, N, ntiles);
}